// round 6
// baseline (speedup 1.0000x reference)
#include <cuda_runtime.h>
#include <math.h>

#define NB 32
#define NH 128
#define HID 5120
#define QLR 1536
#define KVLR 512
#define KVLEN 4096
#define CKVD 576
#define QHD 192

// ----------------------- device scratch (no allocs allowed) -----------------
__device__ __align__(16) float g_qa[NB * QLR];
__device__ __align__(16) float g_qan[NB * QLR];
__device__ __align__(16) float g_q[NB * NH * QHD];
__device__ __align__(16) float g_query[NB * NH * CKVD];
__device__ __align__(16) float g_scores[(size_t)NB * NH * KVLEN]; // 64 MB
__device__ __align__(16) float g_attn[NB * NH * KVLR];
__device__ __align__(16) float g_o[NB * NH * 128];

typedef unsigned long long u64;

__device__ __forceinline__ u64 splat2(float x) {
    u64 r; asm("mov.b64 %0,{%1,%1};" : "=l"(r) : "f"(x)); return r;
}
__device__ __forceinline__ void fma2(u64 &d, u64 a, u64 b) {
    asm("fma.rn.f32x2 %0,%1,%2,%0;" : "+l"(d) : "l"(a), "l"(b));
}
__device__ __forceinline__ float2 unpk(u64 v) {
    float2 f; asm("mov.b64 {%0,%1},%2;" : "=f"(f.x), "=f"(f.y) : "l"(v)); return f;
}

// ---------------------------------------------------------------------------
// NT GEMM: C[m,n] (+)= alpha * sum_k A[m,k] * B[n,k]
// A: row-major [M,K] (lda), B: row-major [N,K] (ldb). Batch via grid.z with
// pointer strides sA/sB/sC. Optional split-K over grid.y with atomic adds.
// Block tile: TM x 64, KC=32, 256 threads. TM in {32,128}.
// ---------------------------------------------------------------------------
template <int TM, bool ATOMIC>
__global__ __launch_bounds__(256) void gemm_nt(
    const float* __restrict__ A, int lda, int sA,
    const float* __restrict__ B, int ldb, int sB,
    float* __restrict__ C, int ldc, int sC,
    int K, float alpha)
{
    constexpr int KC = 32, TN = 64;
    constexpr int P = TM / 32;  // m-pairs per thread

    __shared__ __align__(16) float As[KC][TM + 2];
    __shared__ __align__(16) float Bs[KC][TN + 4];

    const float* Ab = A + (size_t)blockIdx.z * sA;
    const float* Bb = B + (size_t)blockIdx.z * sB;
    float* Cb = C + (size_t)blockIdx.z * sC;

    const int n0 = blockIdx.x * TN;
    const int kseg = K / (int)gridDim.y;
    const int kst = blockIdx.y * kseg;

    const int tid = threadIdx.x;
    const int ng = tid & 15;
    const int mg = tid >> 4;
    const int m0 = mg * 2 * P;

    u64 acc[P][4];
#pragma unroll
    for (int p = 0; p < P; p++)
#pragma unroll
        for (int j = 0; j < 4; j++) acc[p][j] = 0ull;

    for (int kp = kst; kp < kst + kseg; kp += KC) {
        __syncthreads();
#pragma unroll
        for (int i = 0; i < (TM * KC) / 1024; i++) {
            int lin = tid + i * 256;
            int m = lin >> 3, k4 = (lin & 7) * 4;
            float4 v = *(const float4*)(Ab + (size_t)m * lda + kp + k4);
            As[k4 + 0][m] = v.x; As[k4 + 1][m] = v.y;
            As[k4 + 2][m] = v.z; As[k4 + 3][m] = v.w;
        }
#pragma unroll
        for (int i = 0; i < 2; i++) {
            int lin = tid + i * 256;
            int n = lin >> 3, k4 = (lin & 7) * 4;
            float4 v = *(const float4*)(Bb + (size_t)(n0 + n) * ldb + kp + k4);
            Bs[k4 + 0][n] = v.x; Bs[k4 + 1][n] = v.y;
            Bs[k4 + 2][n] = v.z; Bs[k4 + 3][n] = v.w;
        }
        __syncthreads();
#pragma unroll
        for (int kk = 0; kk < KC; kk++) {
            u64 a[P];
            const u64* ar = (const u64*)&As[kk][m0];
#pragma unroll
            for (int p = 0; p < P; p++) a[p] = ar[p];
#pragma unroll
            for (int j = 0; j < 4; j++) {
                u64 bv = splat2(Bs[kk][ng * 4 + j]);
#pragma unroll
                for (int p = 0; p < P; p++) fma2(acc[p][j], a[p], bv);
            }
        }
    }

#pragma unroll
    for (int p = 0; p < P; p++) {
#pragma unroll
        for (int j = 0; j < 4; j++) {
            float2 v = unpk(acc[p][j]);
            int m = m0 + 2 * p, n = n0 + ng * 4 + j;
            if (ATOMIC) {
                atomicAdd(&Cb[(size_t)m * ldc + n], v.x * alpha);
                atomicAdd(&Cb[(size_t)(m + 1) * ldc + n], v.y * alpha);
            } else {
                Cb[(size_t)m * ldc + n] = v.x * alpha;
                Cb[(size_t)(m + 1) * ldc + n] = v.y * alpha;
            }
        }
    }
}

// ---------------------------------------------------------------------------
// NN GEMM: C[m,n] = alpha * sum_k A[m,k] * B[k,n]
// B: row-major [K,N] (ldb). Same tiling as NT otherwise.
// ---------------------------------------------------------------------------
template <int TM>
__global__ __launch_bounds__(256) void gemm_nn(
    const float* __restrict__ A, int lda, int sA,
    const float* __restrict__ B, int ldb, int sB,
    float* __restrict__ C, int ldc, int sC,
    int K, float alpha)
{
    constexpr int KC = 32, TN = 64;
    constexpr int P = TM / 32;

    __shared__ __align__(16) float As[KC][TM + 2];
    __shared__ __align__(16) float Bs[KC][TN + 4];

    const float* Ab = A + (size_t)blockIdx.z * sA;
    const float* Bb = B + (size_t)blockIdx.z * sB;
    float* Cb = C + (size_t)blockIdx.z * sC;

    const int n0 = blockIdx.x * TN;
    const int tid = threadIdx.x;
    const int ng = tid & 15;
    const int mg = tid >> 4;
    const int m0 = mg * 2 * P;

    u64 acc[P][4];
#pragma unroll
    for (int p = 0; p < P; p++)
#pragma unroll
        for (int j = 0; j < 4; j++) acc[p][j] = 0ull;

    for (int kp = 0; kp < K; kp += KC) {
        __syncthreads();
#pragma unroll
        for (int i = 0; i < (TM * KC) / 1024; i++) {
            int lin = tid + i * 256;
            int m = lin >> 3, k4 = (lin & 7) * 4;
            float4 v = *(const float4*)(Ab + (size_t)m * lda + kp + k4);
            As[k4 + 0][m] = v.x; As[k4 + 1][m] = v.y;
            As[k4 + 2][m] = v.z; As[k4 + 3][m] = v.w;
        }
#pragma unroll
        for (int i = 0; i < 2; i++) {
            int lin = tid + i * 256;
            int kk = lin >> 4, n4 = (lin & 15) * 4;
            float4 v = *(const float4*)(Bb + (size_t)(kp + kk) * ldb + n0 + n4);
            *(float4*)&Bs[kk][n4] = v;
        }
        __syncthreads();
#pragma unroll
        for (int kk = 0; kk < KC; kk++) {
            u64 a[P];
            const u64* ar = (const u64*)&As[kk][m0];
#pragma unroll
            for (int p = 0; p < P; p++) a[p] = ar[p];
#pragma unroll
            for (int j = 0; j < 4; j++) {
                u64 bv = splat2(Bs[kk][ng * 4 + j]);
#pragma unroll
                for (int p = 0; p < P; p++) fma2(acc[p][j], a[p], bv);
            }
        }
    }

#pragma unroll
    for (int p = 0; p < P; p++) {
#pragma unroll
        for (int j = 0; j < 4; j++) {
            float2 v = unpk(acc[p][j]);
            int m = m0 + 2 * p, n = n0 + ng * 4 + j;
            Cb[(size_t)m * ldc + n] = v.x * alpha;
            Cb[(size_t)(m + 1) * ldc + n] = v.y * alpha;
        }
    }
}

// ---------------------------------------------------------------------------
__global__ void zero_k(float* __restrict__ p, int n) {
    int i = blockIdx.x * 256 + threadIdx.x;
    if (i < n) p[i] = 0.0f;
}

__global__ __launch_bounds__(256) void rmsnorm_k(
    const float* __restrict__ X, const float* __restrict__ W, float* __restrict__ Y)
{
    __shared__ float red[32];
    int b = blockIdx.x, t = threadIdx.x;
    const float* x = X + b * QLR;
    float s = 0.0f;
    for (int i = t; i < QLR; i += 256) { float v = x[i]; s += v * v; }
    for (int o = 16; o > 0; o >>= 1) s += __shfl_xor_sync(~0u, s, o);
    if ((t & 31) == 0) red[t >> 5] = s;
    __syncthreads();
    if (t < 32) {
        float v = (t < 8) ? red[t] : 0.0f;
        for (int o = 4; o > 0; o >>= 1) v += __shfl_xor_sync(~0u, v, o);
        if (t == 0) red[0] = v;
    }
    __syncthreads();
    float r = rsqrtf(red[0] / (float)QLR + 1e-6f);
    for (int i = t; i < QLR; i += 256) Y[b * QLR + i] = x[i] * r * W[i];
}

// RoPE on q_pe -> g_query[..., 512:576], folding the softmax scale.
__global__ void rope_k(const float* __restrict__ Q, const int* __restrict__ pos,
                       float* __restrict__ QY, float scale)
{
    int bh = blockIdx.x;
    int b = bh >> 7, h = bh & 127;
    int i = threadIdx.x;          // 0..63
    int j = i & 31;
    float p = (float)pos[b];
    float invf = powf(10000.0f, -(float)j / 32.0f);
    float s, c;
    sincosf(p * invf, &s, &c);
    const float* q = Q + (size_t)b * NH * QHD + h * QHD + 128;
    float v;
    if (i < 32) v = q[2 * j] * c - q[2 * j + 1] * s;
    else        v = q[2 * j + 1] * c + q[2 * j] * s;
    QY[(size_t)b * NH * CKVD + h * CKVD + 512 + i] = v * scale;
}

// Row softmax over 4096, in place. One block per (b,h).
__global__ __launch_bounds__(256) void softmax_k(float* __restrict__ S) {
    __shared__ float red[32];
    size_t base = (size_t)blockIdx.x * KVLEN;
    int t = threadIdx.x;
    float4 v[4];
    float mx = -1e30f;
#pragma unroll
    for (int i = 0; i < 4; i++) {
        v[i] = *(float4*)(S + base + t * 4 + i * 1024);
        mx = fmaxf(mx, fmaxf(fmaxf(v[i].x, v[i].y), fmaxf(v[i].z, v[i].w)));
    }
    for (int o = 16; o > 0; o >>= 1) mx = fmaxf(mx, __shfl_xor_sync(~0u, mx, o));
    if ((t & 31) == 0) red[t >> 5] = mx;
    __syncthreads();
    if (t < 32) {
        float m2 = (t < 8) ? red[t] : -1e30f;
        for (int o = 4; o > 0; o >>= 1) m2 = fmaxf(m2, __shfl_xor_sync(~0u, m2, o));
        if (t == 0) red[0] = m2;
    }
    __syncthreads();
    mx = red[0];
    __syncthreads();
    float sum = 0.0f;
#pragma unroll
    for (int i = 0; i < 4; i++) {
        v[i].x = __expf(v[i].x - mx); v[i].y = __expf(v[i].y - mx);
        v[i].z = __expf(v[i].z - mx); v[i].w = __expf(v[i].w - mx);
        sum += v[i].x + v[i].y + v[i].z + v[i].w;
    }
    for (int o = 16; o > 0; o >>= 1) sum += __shfl_xor_sync(~0u, sum, o);
    if ((t & 31) == 0) red[t >> 5] = sum;
    __syncthreads();
    if (t < 32) {
        float s2 = (t < 8) ? red[t] : 0.0f;
        for (int o = 4; o > 0; o >>= 1) s2 += __shfl_xor_sync(~0u, s2, o);
        if (t == 0) red[0] = s2;
    }
    __syncthreads();
    float inv = 1.0f / red[0];
#pragma unroll
    for (int i = 0; i < 4; i++) {
        v[i].x *= inv; v[i].y *= inv; v[i].z *= inv; v[i].w *= inv;
        *(float4*)(S + base + t * 4 + i * 1024) = v[i];
    }
}

// ---------------------------------------------------------------------------
extern "C" void kernel_launch(void* const* d_in, const int* in_sizes, int n_in,
                              void* d_out, int out_size)
{
    const float* hq   = (const float*)d_in[0];
    const int*   pos  = (const int*)d_in[1];
    const float* ckv  = (const float*)d_in[2];
    const float* Wqa  = (const float*)d_in[3];
    const float* lnw  = (const float*)d_in[4];
    const float* Wqb  = (const float*)d_in[5];
    const float* Wkvb = (const float*)d_in[6];
    const float* Wo   = (const float*)d_in[7];
    float* out = (float*)d_out;

    float *qa, *qan, *q, *qry, *sc, *at, *o;
    cudaGetSymbolAddress((void**)&qa,  g_qa);
    cudaGetSymbolAddress((void**)&qan, g_qan);
    cudaGetSymbolAddress((void**)&q,   g_q);
    cudaGetSymbolAddress((void**)&qry, g_query);
    cudaGetSymbolAddress((void**)&sc,  g_scores);
    cudaGetSymbolAddress((void**)&at,  g_attn);
    cudaGetSymbolAddress((void**)&o,   g_o);

    const float scale = 1.0f / sqrtf(192.0f);

    // zero split-K atomic destinations (d_out is poisoned each run)
    zero_k<<<192, 256>>>(qa, NB * QLR);
    zero_k<<<640, 256>>>(out, NB * HID);

    // q_a = hq @ Wq_a^T   [32,1536], K=5120, split-K=4
    gemm_nt<32, true><<<dim3(24, 4, 1), 256>>>(
        hq, HID, 0, Wqa, HID, 0, qa, QLR, 0, HID, 1.0f);

    // rms norm
    rmsnorm_k<<<32, 256>>>(qa, lnw, qan);

    // q = qan @ Wq_b^T    [32,24576], K=1536
    gemm_nt<32, false><<<dim3(384, 1, 1), 256>>>(
        qan, QLR, 0, Wqb, QLR, 0, q, NH * QHD, 0, QLR, 1.0f);

    // RoPE -> query[..., 512:576] (scaled)
    rope_k<<<NB * NH, 64>>>(q, pos, qry, scale);

    // q_lat[b,c] = q_nope[b,:] @ q_absorb[h]  -> query[..., :512] (scaled)
    // per head: M=32, N=512, K=128; B = Wkv_b[h*256 .. h*256+128) rows
    gemm_nn<32><<<dim3(8, 1, NH), 256>>>(
        q, NH * QHD, QHD,
        Wkvb, KVLR, 256 * KVLR,
        qry, NH * CKVD, CKVD,
        128, scale);

    // scores[b][h,k] = query_b @ ckv_b^T : per b M=128, N=4096, K=576
    gemm_nt<128, false><<<dim3(64, 1, NB), 256>>>(
        qry, CKVD, NH * CKVD,
        ckv, CKVD, KVLEN * CKVD,
        sc, KVLEN, NH * KVLEN,
        CKVD, 1.0f);

    // softmax rows
    softmax_k<<<NB * NH, 256>>>(sc);

    // attn[b][h,c] = probs_b @ ckv_b[:, :512] : per b M=128, N=512, K=4096
    gemm_nn<128><<<dim3(8, 1, NB), 256>>>(
        sc, KVLEN, NH * KVLEN,
        ckv, CKVD, KVLEN * CKVD,
        at, KVLR, NH * KVLR,
        KVLEN, 1.0f);

    // o[b][h*128+v] = attn[b,h,:] @ out_absorb[h]^T : per head M=32, N=128, K=512
    gemm_nt<32, false><<<dim3(2, 1, NH), 256>>>(
        at, NH * KVLR, KVLR,
        Wkvb + 128 * KVLR, KVLR, 256 * KVLR,
        o, NH * 128, 128,
        KVLR, 1.0f);

    // out = o @ Wo^T : M=32, N=5120, K=16384, split-K=8
    gemm_nt<32, true><<<dim3(80, 8, 1), 256>>>(
        o, NH * 128, 0, Wo, NH * 128, 0, out, HID, 0, NH * 128, 1.0f);
}

// round 7
// speedup vs baseline: 1.8350x; 1.8350x over previous
#include <cuda_runtime.h>
#include <cuda_bf16.h>
#include <math.h>
#include <stdint.h>

#define NB 32
#define NH 128
#define HID 5120
#define QLR 1536
#define KVLR 512
#define KVLEN 4096
#define CKVD 576
#define QHD 192

// ----------------------- device scratch (no allocs allowed) -----------------
__device__ __align__(16) float g_qa[NB * QLR];
__device__ __align__(16) float g_qan[NB * QLR];
__device__ __align__(16) float g_q[NB * NH * QHD];
__device__ __align__(16) float g_query[NB * NH * CKVD];
__device__ __align__(16) float g_scores[(size_t)NB * NH * KVLEN]; // 64 MB
__device__ __align__(16) float g_attn[NB * NH * KVLR];
__device__ __align__(16) float g_o[NB * NH * 128];

// ----------------------- helpers -------------------------------------------
__device__ __forceinline__ uint32_t pkbf2(float a, float b) {
    __nv_bfloat162 t = __floats2bfloat162_rn(a, b); // .x=a (low), .y=b (high)
    return *(uint32_t*)&t;
}
__device__ __forceinline__ float bfhi(float x) {
    return __bfloat162float(__float2bfloat16_rn(x));
}
__device__ __forceinline__ void mma_bf16(float* c, const uint32_t* a, const uint32_t* b) {
    asm volatile(
        "mma.sync.aligned.m16n8k16.row.col.f32.bf16.bf16.f32 "
        "{%0,%1,%2,%3},{%4,%5,%6,%7},{%8,%9},{%0,%1,%2,%3};\n"
        : "+f"(c[0]), "+f"(c[1]), "+f"(c[2]), "+f"(c[3])
        : "r"(a[0]), "r"(a[1]), "r"(a[2]), "r"(a[3]), "r"(b[0]), "r"(b[1]));
}

// ---------------------------------------------------------------------------
// Tensor-core GEMM, bf16 hi/lo split (3 mma passes), fp32 I/O.
//   BNN=false (NT): C[m,n] = alpha * sum_k A[m,k]*B[n,k]   (B row-major [N,K])
//   BNN=true  (NN): C[m,n] = alpha * sum_k A[m,k]*B[k,n]   (B row-major [K,N])
// CTA tile TM x 128, KC=32, 256 threads (8 warps). Batch via grid.z strides.
// Optional split-K over grid.y with fp32 atomics (caller zeroes C).
// ---------------------------------------------------------------------------
template <int TM, bool BNN, bool ATOMIC>
__global__ __launch_bounds__(256, 1) void mmagemm(
    const float* __restrict__ A, int lda, int sA,
    const float* __restrict__ B, int ldb, int sB,
    float* __restrict__ C, int ldc, int sC,
    int K, float alpha)
{
    constexpr int KC = 32;
    constexpr int WM = (TM == 128) ? 4 : 2;     // warp grid m
    constexpr int MS = TM / (WM * 16);          // m16 subtiles / warp
    constexpr int NS = 128 / ((8 / WM) * 8);    // n8 subtiles / warp
    constexpr int APF = (TM * KC) / 1024;       // A float4 / thread

    __shared__ __align__(16) __nv_bfloat16 AsH[TM][34];
    __shared__ __align__(16) __nv_bfloat16 AsL[TM][34];
    __shared__ __align__(16) __nv_bfloat16 BsH[128][34];
    __shared__ __align__(16) __nv_bfloat16 BsL[128][34];

    const float* Ab = A + (size_t)blockIdx.z * sA;
    const float* Bb = B + (size_t)blockIdx.z * sB;
    float* Cb = C + (size_t)blockIdx.z * sC;

    const int n0 = blockIdx.x * 128;
    const int kseg = K / (int)gridDim.y;
    const int kst = blockIdx.y * kseg;

    const int tid = threadIdx.x;
    const int lane = tid & 31;
    const int warp = tid >> 5;
    const int wm = (TM == 128) ? ((warp >> 1) * 32) : ((warp & 1) * 16);
    const int wn = (TM == 128) ? ((warp & 1) * 64) : ((warp >> 1) * 32);
    const int fr = lane >> 2;       // 0..7
    const int fc = (lane & 3) * 2;  // 0,2,4,6

    float acc[MS][NS][4];
#pragma unroll
    for (int i = 0; i < MS; i++)
#pragma unroll
        for (int j = 0; j < NS; j++)
#pragma unroll
            for (int q = 0; q < 4; q++) acc[i][j][q] = 0.0f;

    float4 pa[APF];
    float4 pbt[4];                 // NT B prefetch
    float4 pb0[2], pb1[2];         // NN B prefetch (k-row pairs)

    auto loadA = [&](int kp) {
#pragma unroll
        for (int i = 0; i < APF; i++) {
            int lin = tid + i * 256;
            int r = lin >> 3, k4 = (lin & 7) * 4;
            pa[i] = *(const float4*)(Ab + (size_t)r * lda + kp + k4);
        }
    };
    auto storeA = [&]() {
#pragma unroll
        for (int i = 0; i < APF; i++) {
            int lin = tid + i * 256;
            int r = lin >> 3, k4 = (lin & 7) * 4;
            float4 v = pa[i];
            float hx = bfhi(v.x), hy = bfhi(v.y), hz = bfhi(v.z), hw = bfhi(v.w);
            uint32_t* dh = (uint32_t*)&AsH[r][k4];
            uint32_t* dl = (uint32_t*)&AsL[r][k4];
            dh[0] = pkbf2(hx, hy); dh[1] = pkbf2(hz, hw);
            dl[0] = pkbf2(v.x - hx, v.y - hy); dl[1] = pkbf2(v.z - hz, v.w - hw);
        }
    };
    auto loadB = [&](int kp) {
        if (BNN) {
#pragma unroll
            for (int g = 0; g < 2; g++) {
                int slot = tid + g * 256;
                int kpp = slot >> 5;            // 0..15 (k-pair)
                int n = (slot & 31) * 4;
                const float* r0 = Bb + (size_t)(kp + 2 * kpp) * ldb + n0 + n;
                pb0[g] = *(const float4*)r0;
                pb1[g] = *(const float4*)(r0 + ldb);
            }
        } else {
#pragma unroll
            for (int i = 0; i < 4; i++) {
                int lin = tid + i * 256;
                int nr = lin >> 3, k4 = (lin & 7) * 4;
                pbt[i] = *(const float4*)(Bb + (size_t)(n0 + nr) * ldb + kp + k4);
            }
        }
    };
    auto storeB = [&]() {
        if (BNN) {
#pragma unroll
            for (int g = 0; g < 2; g++) {
                int slot = tid + g * 256;
                int kpp = slot >> 5;
                int n = (slot & 31) * 4;
                float r0[4] = {pb0[g].x, pb0[g].y, pb0[g].z, pb0[g].w};
                float r1[4] = {pb1[g].x, pb1[g].y, pb1[g].z, pb1[g].w};
#pragma unroll
                for (int j = 0; j < 4; j++) {
                    int nn = n + j;
                    int w = kpp ^ ((nn >> 3) & 15);  // bank swizzle
                    float h0 = bfhi(r0[j]), h1 = bfhi(r1[j]);
                    *(uint32_t*)((char*)&BsH[0][0] + nn * 68 + 4 * w) = pkbf2(h0, h1);
                    *(uint32_t*)((char*)&BsL[0][0] + nn * 68 + 4 * w) =
                        pkbf2(r0[j] - h0, r1[j] - h1);
                }
            }
        } else {
#pragma unroll
            for (int i = 0; i < 4; i++) {
                int lin = tid + i * 256;
                int nr = lin >> 3, k4 = (lin & 7) * 4;
                float4 v = pbt[i];
                float hx = bfhi(v.x), hy = bfhi(v.y), hz = bfhi(v.z), hw = bfhi(v.w);
                uint32_t* dh = (uint32_t*)&BsH[nr][k4];
                uint32_t* dl = (uint32_t*)&BsL[nr][k4];
                dh[0] = pkbf2(hx, hy); dh[1] = pkbf2(hz, hw);
                dl[0] = pkbf2(v.x - hx, v.y - hy); dl[1] = pkbf2(v.z - hz, v.w - hw);
            }
        }
    };

    loadA(kst);
    loadB(kst);

    const int kend = kst + kseg;
    for (int kp = kst; kp < kend; kp += KC) {
        __syncthreads();
        storeA();
        storeB();
        __syncthreads();
        if (kp + KC < kend) { loadA(kp + KC); loadB(kp + KC); }

#pragma unroll
        for (int k16 = 0; k16 < KC; k16 += 16) {
            uint32_t aH[MS][4], aL[MS][4];
#pragma unroll
            for (int ms = 0; ms < MS; ms++) {
                int ra = wm + ms * 16 + fr;
                aH[ms][0] = *(uint32_t*)&AsH[ra][k16 + fc];
                aH[ms][1] = *(uint32_t*)&AsH[ra + 8][k16 + fc];
                aH[ms][2] = *(uint32_t*)&AsH[ra][k16 + fc + 8];
                aH[ms][3] = *(uint32_t*)&AsH[ra + 8][k16 + fc + 8];
                aL[ms][0] = *(uint32_t*)&AsL[ra][k16 + fc];
                aL[ms][1] = *(uint32_t*)&AsL[ra + 8][k16 + fc];
                aL[ms][2] = *(uint32_t*)&AsL[ra][k16 + fc + 8];
                aL[ms][3] = *(uint32_t*)&AsL[ra + 8][k16 + fc + 8];
            }
#pragma unroll
            for (int ns = 0; ns < NS; ns++) {
                int cB = wn + ns * 8 + fr;
                int w0 = (k16 >> 1) + (lane & 3);
                int w1 = w0 + 4;
                if (BNN) {
                    int s = (cB >> 3) & 15;
                    w0 ^= s; w1 ^= s;
                }
                uint32_t bH[2], bL[2];
                bH[0] = *(uint32_t*)((char*)&BsH[0][0] + cB * 68 + 4 * w0);
                bH[1] = *(uint32_t*)((char*)&BsH[0][0] + cB * 68 + 4 * w1);
                bL[0] = *(uint32_t*)((char*)&BsL[0][0] + cB * 68 + 4 * w0);
                bL[1] = *(uint32_t*)((char*)&BsL[0][0] + cB * 68 + 4 * w1);
#pragma unroll
                for (int ms = 0; ms < MS; ms++) {
                    mma_bf16(acc[ms][ns], aH[ms], bH);
                    mma_bf16(acc[ms][ns], aH[ms], bL);
                    mma_bf16(acc[ms][ns], aL[ms], bH);
                }
            }
        }
    }

#pragma unroll
    for (int ms = 0; ms < MS; ms++) {
#pragma unroll
        for (int ns = 0; ns < NS; ns++) {
            int cr = wm + ms * 16 + fr;
            int cc = n0 + wn + ns * 8 + (lane & 3) * 2;
            float v0 = acc[ms][ns][0] * alpha, v1 = acc[ms][ns][1] * alpha;
            float v2 = acc[ms][ns][2] * alpha, v3 = acc[ms][ns][3] * alpha;
            if (ATOMIC) {
                atomicAdd(&Cb[(size_t)cr * ldc + cc], v0);
                atomicAdd(&Cb[(size_t)cr * ldc + cc + 1], v1);
                atomicAdd(&Cb[(size_t)(cr + 8) * ldc + cc], v2);
                atomicAdd(&Cb[(size_t)(cr + 8) * ldc + cc + 1], v3);
            } else {
                float2 p0 = {v0, v1}, p1 = {v2, v3};
                *(float2*)&Cb[(size_t)cr * ldc + cc] = p0;
                *(float2*)&Cb[(size_t)(cr + 8) * ldc + cc] = p1;
            }
        }
    }
}

// ---------------------------------------------------------------------------
__global__ void zero_k(float* __restrict__ p, int n) {
    int i = blockIdx.x * 256 + threadIdx.x;
    if (i < n) p[i] = 0.0f;
}

__global__ __launch_bounds__(256) void rmsnorm_k(
    const float* __restrict__ X, const float* __restrict__ W, float* __restrict__ Y)
{
    __shared__ float red[32];
    int b = blockIdx.x, t = threadIdx.x;
    const float* x = X + b * QLR;
    float s = 0.0f;
    for (int i = t; i < QLR; i += 256) { float v = x[i]; s += v * v; }
    for (int o = 16; o > 0; o >>= 1) s += __shfl_xor_sync(~0u, s, o);
    if ((t & 31) == 0) red[t >> 5] = s;
    __syncthreads();
    if (t < 32) {
        float v = (t < 8) ? red[t] : 0.0f;
        for (int o = 4; o > 0; o >>= 1) v += __shfl_xor_sync(~0u, v, o);
        if (t == 0) red[0] = v;
    }
    __syncthreads();
    float r = rsqrtf(red[0] / (float)QLR + 1e-6f);
    for (int i = t; i < QLR; i += 256) Y[b * QLR + i] = x[i] * r * W[i];
}

__global__ void rope_k(const float* __restrict__ Q, const int* __restrict__ pos,
                       float* __restrict__ QY, float scale)
{
    int bh = blockIdx.x;
    int b = bh >> 7, h = bh & 127;
    int i = threadIdx.x;          // 0..63
    int j = i & 31;
    float p = (float)pos[b];
    float invf = powf(10000.0f, -(float)j / 32.0f);
    float s, c;
    sincosf(p * invf, &s, &c);
    const float* q = Q + (size_t)b * NH * QHD + h * QHD + 128;
    float v;
    if (i < 32) v = q[2 * j] * c - q[2 * j + 1] * s;
    else        v = q[2 * j + 1] * c + q[2 * j] * s;
    QY[(size_t)b * NH * CKVD + h * CKVD + 512 + i] = v * scale;
}

__global__ __launch_bounds__(256) void softmax_k(float* __restrict__ S) {
    __shared__ float red[32];
    size_t base = (size_t)blockIdx.x * KVLEN;
    int t = threadIdx.x;
    float4 v[4];
    float mx = -1e30f;
#pragma unroll
    for (int i = 0; i < 4; i++) {
        v[i] = *(float4*)(S + base + t * 4 + i * 1024);
        mx = fmaxf(mx, fmaxf(fmaxf(v[i].x, v[i].y), fmaxf(v[i].z, v[i].w)));
    }
    for (int o = 16; o > 0; o >>= 1) mx = fmaxf(mx, __shfl_xor_sync(~0u, mx, o));
    if ((t & 31) == 0) red[t >> 5] = mx;
    __syncthreads();
    if (t < 32) {
        float m2 = (t < 8) ? red[t] : -1e30f;
        for (int o = 4; o > 0; o >>= 1) m2 = fmaxf(m2, __shfl_xor_sync(~0u, m2, o));
        if (t == 0) red[0] = m2;
    }
    __syncthreads();
    mx = red[0];
    __syncthreads();
    float sum = 0.0f;
#pragma unroll
    for (int i = 0; i < 4; i++) {
        v[i].x = __expf(v[i].x - mx); v[i].y = __expf(v[i].y - mx);
        v[i].z = __expf(v[i].z - mx); v[i].w = __expf(v[i].w - mx);
        sum += v[i].x + v[i].y + v[i].z + v[i].w;
    }
    for (int o = 16; o > 0; o >>= 1) sum += __shfl_xor_sync(~0u, sum, o);
    if ((t & 31) == 0) red[t >> 5] = sum;
    __syncthreads();
    if (t < 32) {
        float s2 = (t < 8) ? red[t] : 0.0f;
        for (int o = 4; o > 0; o >>= 1) s2 += __shfl_xor_sync(~0u, s2, o);
        if (t == 0) red[0] = s2;
    }
    __syncthreads();
    float inv = 1.0f / red[0];
#pragma unroll
    for (int i = 0; i < 4; i++) {
        v[i].x *= inv; v[i].y *= inv; v[i].z *= inv; v[i].w *= inv;
        *(float4*)(S + base + t * 4 + i * 1024) = v[i];
    }
}

// ---------------------------------------------------------------------------
extern "C" void kernel_launch(void* const* d_in, const int* in_sizes, int n_in,
                              void* d_out, int out_size)
{
    const float* hq   = (const float*)d_in[0];
    const int*   pos  = (const int*)d_in[1];
    const float* ckv  = (const float*)d_in[2];
    const float* Wqa  = (const float*)d_in[3];
    const float* lnw  = (const float*)d_in[4];
    const float* Wqb  = (const float*)d_in[5];
    const float* Wkvb = (const float*)d_in[6];
    const float* Wo   = (const float*)d_in[7];
    float* out = (float*)d_out;

    float *qa, *qan, *q, *qry, *sc, *at, *o;
    cudaGetSymbolAddress((void**)&qa,  g_qa);
    cudaGetSymbolAddress((void**)&qan, g_qan);
    cudaGetSymbolAddress((void**)&q,   g_q);
    cudaGetSymbolAddress((void**)&qry, g_query);
    cudaGetSymbolAddress((void**)&sc,  g_scores);
    cudaGetSymbolAddress((void**)&at,  g_attn);
    cudaGetSymbolAddress((void**)&o,   g_o);

    const float scale = 1.0f / sqrtf(192.0f);

    // zero split-K atomic destinations
    zero_k<<<192, 256>>>(qa, NB * QLR);
    zero_k<<<640, 256>>>(out, NB * HID);

    // q_a = hq @ Wq_a^T : M=32, N=1536, K=5120, split-K=8
    mmagemm<32, false, true><<<dim3(12, 8, 1), 256>>>(
        hq, HID, 0, Wqa, HID, 0, qa, QLR, 0, HID, 1.0f);

    rmsnorm_k<<<32, 256>>>(qa, lnw, qan);

    // q = qan @ Wq_b^T : M=32, N=24576, K=1536
    mmagemm<32, false, false><<<dim3(192, 1, 1), 256>>>(
        qan, QLR, 0, Wqb, QLR, 0, q, NH * QHD, 0, QLR, 1.0f);

    // RoPE -> query[..., 512:576] (scaled)
    rope_k<<<NB * NH, 64>>>(q, pos, qry, scale);

    // q_lat: per head M=32, N=512, K=128 (NN vs q_absorb)
    mmagemm<32, true, false><<<dim3(4, 1, NH), 256>>>(
        q, NH * QHD, QHD,
        Wkvb, KVLR, 256 * KVLR,
        qry, NH * CKVD, CKVD,
        128, scale);

    // scores: per b M=128(heads), N=4096, K=576 (NT vs ckv)
    mmagemm<128, false, false><<<dim3(32, 1, NB), 256>>>(
        qry, CKVD, NH * CKVD,
        ckv, CKVD, KVLEN * CKVD,
        sc, KVLEN, NH * KVLEN,
        CKVD, 1.0f);

    softmax_k<<<NB * NH, 256>>>(sc);

    // attn: per b M=128, N=512, K=4096 (NN vs ckv[:, :512])
    mmagemm<128, true, false><<<dim3(4, 1, NB), 256>>>(
        sc, KVLEN, NH * KVLEN,
        ckv, CKVD, KVLEN * CKVD,
        at, KVLR, NH * KVLR,
        KVLEN, 1.0f);

    // o: per head M=32, N=128, K=512 (NT vs out_absorb)
    mmagemm<32, false, false><<<dim3(1, 1, NH), 256>>>(
        at, NH * KVLR, KVLR,
        Wkvb + 128 * KVLR, KVLR, 256 * KVLR,
        o, NH * 128, 128,
        KVLR, 1.0f);

    // out = o @ Wo^T : M=32, N=5120, K=16384, split-K=8
    mmagemm<32, false, true><<<dim3(40, 8, 1), 256>>>(
        o, NH * 128, 0, Wo, NH * 128, 0, out, HID, 0, NH * 128, 1.0f);
}

// round 11
// speedup vs baseline: 1.9897x; 1.0843x over previous
#include <cuda_runtime.h>
#include <cuda_bf16.h>
#include <math.h>
#include <stdint.h>

#define NB 32
#define NH 128
#define HID 5120
#define QLR 1536
#define KVLR 512
#define KVLEN 4096
#define CKVD 576
#define QHD 192

// ----------------------- device scratch (no allocs allowed) -----------------
__device__ __align__(16) float g_qa[NB * QLR];
__device__ __align__(16) float g_qan[NB * QLR];
__device__ __align__(16) float g_q[NB * NH * QHD];
__device__ __align__(16) float g_query[NB * NH * CKVD];
__device__ __align__(16) float g_scores[(size_t)NB * NH * KVLEN];   // 64 MB
__device__ __align__(16) float g_attn[NB * NH * KVLR];
__device__ __align__(16) float g_o[NB * NH * 128];

__device__ __align__(16) __nv_bfloat16 g_ckvH[(size_t)NB * KVLEN * CKVD];  // 151 MB
__device__ __align__(16) __nv_bfloat16 g_ckvL[(size_t)NB * KVLEN * CKVD];  // 151 MB
__device__ __align__(16) __nv_bfloat16 g_qryH[NB * NH * CKVD];
__device__ __align__(16) __nv_bfloat16 g_qryL[NB * NH * CKVD];
__device__ __align__(16) __nv_bfloat16 g_prH[(size_t)NB * NH * KVLEN];     // 33.5 MB
__device__ __align__(16) __nv_bfloat16 g_prL[(size_t)NB * NH * KVLEN];     // 33.5 MB

// ----------------------- helpers -------------------------------------------
__device__ __forceinline__ uint32_t pkbf2(float a, float b) {
    __nv_bfloat162 t = __floats2bfloat162_rn(a, b);
    return *(uint32_t*)&t;
}
__device__ __forceinline__ float bfhi(float x) {
    return __bfloat162float(__float2bfloat16_rn(x));
}
__device__ __forceinline__ void mma_bf16(float* c, const uint32_t* a, const uint32_t* b) {
    asm volatile(
        "mma.sync.aligned.m16n8k16.row.col.f32.bf16.bf16.f32 "
        "{%0,%1,%2,%3},{%4,%5,%6,%7},{%8,%9},{%0,%1,%2,%3};\n"
        : "+f"(c[0]), "+f"(c[1]), "+f"(c[2]), "+f"(c[3])
        : "r"(a[0]), "r"(a[1]), "r"(a[2]), "r"(a[3]), "r"(b[0]), "r"(b[1]));
}
// pack 2 fp32 -> bf16x2 hi (lo-half=a) plus residual bf16x2
__device__ __forceinline__ void cvt2(float a, float b, uint32_t& H, uint32_t& L) {
    asm("cvt.rn.satfinite.bf16x2.f32 %0, %1, %2;" : "=r"(H) : "f"(b), "f"(a));
    float ha = __uint_as_float(H << 16);
    float hb = __uint_as_float(H & 0xffff0000u);
    asm("cvt.rn.satfinite.bf16x2.f32 %0, %1, %2;" : "=r"(L) : "f"(b - hb), "f"(a - ha));
}
__device__ __forceinline__ uint32_t smem_u32(const void* p) {
    uint32_t a;
    asm("{ .reg .u64 t; cvta.to.shared.u64 t, %1; cvt.u32.u64 %0, t; }"
        : "=r"(a) : "l"(p));
    return a;
}
__device__ __forceinline__ void cpasync(uint32_t s, const void* g) {
    asm volatile("cp.async.cg.shared.global [%0],[%1],16;" :: "r"(s), "l"(g) : "memory");
}
#define CP_COMMIT() asm volatile("cp.async.commit_group;" ::: "memory")
#define LDSM4(r, ad) \
    asm volatile("ldmatrix.sync.aligned.m8n8.x4.shared.b16 {%0,%1,%2,%3},[%4];" \
        : "=r"((r)[0]), "=r"((r)[1]), "=r"((r)[2]), "=r"((r)[3]) : "r"(ad))
#define LDSM4T(r, ad) \
    asm volatile("ldmatrix.sync.aligned.m8n8.x4.trans.shared.b16 {%0,%1,%2,%3},[%4];" \
        : "=r"((r)[0]), "=r"((r)[1]), "=r"((r)[2]), "=r"((r)[3]) : "r"(ad))

#define PIPE_SMEM 196608   /* 3 stages x 64KB */

// ---------------------------------------------------------------------------
// Pipelined bf16 hi/lo GEMM on pre-split planes. C fp32 = sum of 3 passes.
//   BT=false: B planes are [n][k] rows (NT).  BT=true: B planes are [k][n] (NN).
// CTA tile 128x128, KC=64, 256 threads, 3-stage cp.async pipeline.
// grid.x = N/128 tiles, grid.y = batch.
// ---------------------------------------------------------------------------
template <bool BT>
__global__ __launch_bounds__(256, 1) void pipegemm(
    const __nv_bfloat16* __restrict__ AH, const __nv_bfloat16* __restrict__ AL,
    int lda, int sA,
    const __nv_bfloat16* __restrict__ BH, const __nv_bfloat16* __restrict__ BL,
    int ldb, int sB,
    float* __restrict__ C, int ldc, int sC, int K)
{
    extern __shared__ __align__(1024) char sm[];
    const uint32_t sb = smem_u32(sm);
    const int tid = threadIdx.x, lane = tid & 31, warp = tid >> 5;
    const int b = blockIdx.y;
    const __nv_bfloat16* AHb = AH + (size_t)b * sA;
    const __nv_bfloat16* ALb = AL + (size_t)b * sA;
    const __nv_bfloat16* BHb = BH + (size_t)b * sB;
    const __nv_bfloat16* BLb = BL + (size_t)b * sB;
    float* Cb = C + (size_t)b * sC;
    const int n0 = blockIdx.x * 128;
    const int nslab = K >> 6;

    const int wm = (warp >> 1) * 32;
    const int wn = (warp & 1) * 64;

    float acc[2][8][4];
#pragma unroll
    for (int i = 0; i < 2; i++)
#pragma unroll
        for (int j = 0; j < 8; j++)
#pragma unroll
            for (int q = 0; q < 4; q++) acc[i][j][q] = 0.0f;

    auto issue = [&](int s) {
        const int kp = s * 64;
        const uint32_t st = sb + (s % 3) * 65536;
        // A tile: 128 rows x 64 bf16 (128B rows, 8 chunks)
#pragma unroll
        for (int i = 0; i < 4; i++) {
            int lin = tid + i * 256;
            int r = lin >> 3, c = lin & 7;
            uint32_t so = st + r * 128 + ((c ^ (r & 7)) << 4);
            const char* gh = (const char*)(AHb + (size_t)r * lda + kp) + (c << 4);
            const char* gl = (const char*)(ALb + (size_t)r * lda + kp) + (c << 4);
            cpasync(so, gh);
            cpasync(so + 16384, gl);
        }
        if (BT) {
            // B tile: 64 k-rows x 128 bf16 (256B rows, 16 chunks)
#pragma unroll
            for (int i = 0; i < 4; i++) {
                int lin = tid + i * 256;
                int r = lin >> 4, c = lin & 15;
                uint32_t so = st + 32768 + r * 256 + ((c ^ (r & 7)) << 4);
                const char* gh = (const char*)(BHb + (size_t)(kp + r) * ldb + n0) + (c << 4);
                const char* gl = (const char*)(BLb + (size_t)(kp + r) * ldb + n0) + (c << 4);
                cpasync(so, gh);
                cpasync(so + 16384, gl);
            }
        } else {
            // B tile: 128 n-rows x 64 bf16 (128B rows, 8 chunks)
#pragma unroll
            for (int i = 0; i < 4; i++) {
                int lin = tid + i * 256;
                int r = lin >> 3, c = lin & 7;
                uint32_t so = st + 32768 + r * 128 + ((c ^ (r & 7)) << 4);
                const char* gh = (const char*)(BHb + (size_t)(n0 + r) * ldb + kp) + (c << 4);
                const char* gl = (const char*)(BLb + (size_t)(n0 + r) * ldb + kp) + (c << 4);
                cpasync(so, gh);
                cpasync(so + 16384, gl);
            }
        }
        CP_COMMIT();
    };

    issue(0);
    if (nslab > 1) issue(1);

    for (int s = 0; s < nslab; s++) {
        if (s + 2 < nslab) {
            issue(s + 2);
            asm volatile("cp.async.wait_group 2;" ::: "memory");
        } else if (s + 1 < nslab) {
            asm volatile("cp.async.wait_group 1;" ::: "memory");
        } else {
            asm volatile("cp.async.wait_group 0;" ::: "memory");
        }
        __syncthreads();
        const uint32_t st = sb + (s % 3) * 65536;

#pragma unroll
        for (int kk = 0; kk < 4; kk++) {
            uint32_t aH[2][4], aL[2][4];
#pragma unroll
            for (int ms = 0; ms < 2; ms++) {
                int r = wm + ms * 16 + ((lane >> 3) & 1) * 8 + (lane & 7);
                int c = 2 * kk + (lane >> 4);
                uint32_t ad = st + r * 128 + ((c ^ (r & 7)) << 4);
                LDSM4(aH[ms], ad);
                LDSM4(aL[ms], ad + 16384);
            }
            uint32_t bH[8][2], bL[8][2];
            if (BT) {
#pragma unroll
                for (int j = 0; j < 4; j++) {
                    int r = kk * 16 + ((lane >> 3) & 1) * 8 + (lane & 7);
                    int c = (wn >> 3) + 2 * j + (lane >> 4);
                    uint32_t ad = st + 32768 + r * 256 + ((c ^ (r & 7)) << 4);
                    uint32_t t[4], u[4];
                    LDSM4T(t, ad);
                    LDSM4T(u, ad + 16384);
                    bH[2 * j][0] = t[0]; bH[2 * j][1] = t[1];
                    bH[2 * j + 1][0] = t[2]; bH[2 * j + 1][1] = t[3];
                    bL[2 * j][0] = u[0]; bL[2 * j][1] = u[1];
                    bL[2 * j + 1][0] = u[2]; bL[2 * j + 1][1] = u[3];
                }
            } else {
#pragma unroll
                for (int j = 0; j < 4; j++) {
                    int r = wn + j * 16 + ((lane >> 4) & 1) * 8 + (lane & 7);
                    int c = 2 * kk + ((lane >> 3) & 1);
                    uint32_t ad = st + 32768 + r * 128 + ((c ^ (r & 7)) << 4);
                    uint32_t t[4], u[4];
                    LDSM4(t, ad);
                    LDSM4(u, ad + 16384);
                    bH[2 * j][0] = t[0]; bH[2 * j][1] = t[1];
                    bH[2 * j + 1][0] = t[2]; bH[2 * j + 1][1] = t[3];
                    bL[2 * j][0] = u[0]; bL[2 * j][1] = u[1];
                    bL[2 * j + 1][0] = u[2]; bL[2 * j + 1][1] = u[3];
                }
            }
#pragma unroll
            for (int ns = 0; ns < 8; ns++) {
#pragma unroll
                for (int ms = 0; ms < 2; ms++) {
                    mma_bf16(acc[ms][ns], aH[ms], bH[ns]);
                    mma_bf16(acc[ms][ns], aH[ms], bL[ns]);
                    mma_bf16(acc[ms][ns], aL[ms], bH[ns]);
                }
            }
        }
        __syncthreads();
    }

#pragma unroll
    for (int ms = 0; ms < 2; ms++) {
#pragma unroll
        for (int ns = 0; ns < 8; ns++) {
            int r = wm + ms * 16 + (lane >> 2);
            int c = n0 + wn + ns * 8 + (lane & 3) * 2;
            float2 p0 = {acc[ms][ns][0], acc[ms][ns][1]};
            float2 p1 = {acc[ms][ns][2], acc[ms][ns][3]};
            *(float2*)&Cb[(size_t)r * ldc + c] = p0;
            *(float2*)&Cb[(size_t)(r + 8) * ldc + c] = p1;
        }
    }
}

// ---------------------------------------------------------------------------
// fp32 plane -> bf16 hi/lo planes
// ---------------------------------------------------------------------------
__global__ void cvt_plane(const float4* __restrict__ X, uint2* __restrict__ H,
                          uint2* __restrict__ L, int n4)
{
    int i = blockIdx.x * 256 + threadIdx.x;
    int stride = gridDim.x * 256;
    for (; i < n4; i += stride) {
        float4 v = X[i];
        uint32_t h0, l0, h1, l1;
        cvt2(v.x, v.y, h0, l0);
        cvt2(v.z, v.w, h1, l1);
        H[i] = make_uint2(h0, h1);
        L[i] = make_uint2(l0, l1);
    }
}

// ---------------------------------------------------------------------------
// mma.sync GEMM for small M=32 weight GEMMs (proven R6 path)
// ---------------------------------------------------------------------------
template <int TM, bool BNN, bool ATOMIC>
__global__ __launch_bounds__(256, 1) void mmagemm(
    const float* __restrict__ A, int lda, int sA,
    const float* __restrict__ B, int ldb, int sB,
    float* __restrict__ C, int ldc, int sC,
    int K, float alpha)
{
    constexpr int KC = 32;
    constexpr int WM = (TM == 128) ? 4 : 2;
    constexpr int MS = TM / (WM * 16);
    constexpr int NS = 128 / ((8 / WM) * 8);
    constexpr int APF = (TM * KC) / 1024;

    __shared__ __align__(16) __nv_bfloat16 AsH[TM][34];
    __shared__ __align__(16) __nv_bfloat16 AsL[TM][34];
    __shared__ __align__(16) __nv_bfloat16 BsH[128][34];
    __shared__ __align__(16) __nv_bfloat16 BsL[128][34];

    const float* Ab = A + (size_t)blockIdx.z * sA;
    const float* Bb = B + (size_t)blockIdx.z * sB;
    float* Cb = C + (size_t)blockIdx.z * sC;

    const int n0 = blockIdx.x * 128;
    const int kseg = K / (int)gridDim.y;
    const int kst = blockIdx.y * kseg;

    const int tid = threadIdx.x;
    const int lane = tid & 31;
    const int warp = tid >> 5;
    const int wm = (TM == 128) ? ((warp >> 1) * 32) : ((warp & 1) * 16);
    const int wn = (TM == 128) ? ((warp & 1) * 64) : ((warp >> 1) * 32);
    const int fr = lane >> 2;
    const int fc = (lane & 3) * 2;

    float acc[MS][NS][4];
#pragma unroll
    for (int i = 0; i < MS; i++)
#pragma unroll
        for (int j = 0; j < NS; j++)
#pragma unroll
            for (int q = 0; q < 4; q++) acc[i][j][q] = 0.0f;

    float4 pa[APF];
    float4 pbt[4];
    float4 pb0[2], pb1[2];

    auto loadA = [&](int kp) {
#pragma unroll
        for (int i = 0; i < APF; i++) {
            int lin = tid + i * 256;
            int r = lin >> 3, k4 = (lin & 7) * 4;
            pa[i] = *(const float4*)(Ab + (size_t)r * lda + kp + k4);
        }
    };
    auto storeA = [&]() {
#pragma unroll
        for (int i = 0; i < APF; i++) {
            int lin = tid + i * 256;
            int r = lin >> 3, k4 = (lin & 7) * 4;
            float4 v = pa[i];
            float hx = bfhi(v.x), hy = bfhi(v.y), hz = bfhi(v.z), hw = bfhi(v.w);
            uint32_t* dh = (uint32_t*)&AsH[r][k4];
            uint32_t* dl = (uint32_t*)&AsL[r][k4];
            dh[0] = pkbf2(hx, hy); dh[1] = pkbf2(hz, hw);
            dl[0] = pkbf2(v.x - hx, v.y - hy); dl[1] = pkbf2(v.z - hz, v.w - hw);
        }
    };
    auto loadB = [&](int kp) {
        if (BNN) {
#pragma unroll
            for (int g = 0; g < 2; g++) {
                int slot = tid + g * 256;
                int kpp = slot >> 5;
                int n = (slot & 31) * 4;
                const float* r0 = Bb + (size_t)(kp + 2 * kpp) * ldb + n0 + n;
                pb0[g] = *(const float4*)r0;
                pb1[g] = *(const float4*)(r0 + ldb);
            }
        } else {
#pragma unroll
            for (int i = 0; i < 4; i++) {
                int lin = tid + i * 256;
                int nr = lin >> 3, k4 = (lin & 7) * 4;
                pbt[i] = *(const float4*)(Bb + (size_t)(n0 + nr) * ldb + kp + k4);
            }
        }
    };
    auto storeB = [&]() {
        if (BNN) {
#pragma unroll
            for (int g = 0; g < 2; g++) {
                int slot = tid + g * 256;
                int kpp = slot >> 5;
                int n = (slot & 31) * 4;
                float r0[4] = {pb0[g].x, pb0[g].y, pb0[g].z, pb0[g].w};
                float r1[4] = {pb1[g].x, pb1[g].y, pb1[g].z, pb1[g].w};
#pragma unroll
                for (int j = 0; j < 4; j++) {
                    int nn = n + j;
                    int w = kpp ^ ((nn >> 3) & 15);
                    float h0 = bfhi(r0[j]), h1 = bfhi(r1[j]);
                    *(uint32_t*)((char*)&BsH[0][0] + nn * 68 + 4 * w) = pkbf2(h0, h1);
                    *(uint32_t*)((char*)&BsL[0][0] + nn * 68 + 4 * w) =
                        pkbf2(r0[j] - h0, r1[j] - h1);
                }
            }
        } else {
#pragma unroll
            for (int i = 0; i < 4; i++) {
                int lin = tid + i * 256;
                int nr = lin >> 3, k4 = (lin & 7) * 4;
                float4 v = pbt[i];
                float hx = bfhi(v.x), hy = bfhi(v.y), hz = bfhi(v.z), hw = bfhi(v.w);
                uint32_t* dh = (uint32_t*)&BsH[nr][k4];
                uint32_t* dl = (uint32_t*)&BsL[nr][k4];
                dh[0] = pkbf2(hx, hy); dh[1] = pkbf2(hz, hw);
                dl[0] = pkbf2(v.x - hx, v.y - hy); dl[1] = pkbf2(v.z - hz, v.w - hw);
            }
        }
    };

    loadA(kst);
    loadB(kst);

    const int kend = kst + kseg;
    for (int kp = kst; kp < kend; kp += KC) {
        __syncthreads();
        storeA();
        storeB();
        __syncthreads();
        if (kp + KC < kend) { loadA(kp + KC); loadB(kp + KC); }

#pragma unroll
        for (int k16 = 0; k16 < KC; k16 += 16) {
            uint32_t aH[MS][4], aL[MS][4];
#pragma unroll
            for (int ms = 0; ms < MS; ms++) {
                int ra = wm + ms * 16 + fr;
                aH[ms][0] = *(uint32_t*)&AsH[ra][k16 + fc];
                aH[ms][1] = *(uint32_t*)&AsH[ra + 8][k16 + fc];
                aH[ms][2] = *(uint32_t*)&AsH[ra][k16 + fc + 8];
                aH[ms][3] = *(uint32_t*)&AsH[ra + 8][k16 + fc + 8];
                aL[ms][0] = *(uint32_t*)&AsL[ra][k16 + fc];
                aL[ms][1] = *(uint32_t*)&AsL[ra + 8][k16 + fc];
                aL[ms][2] = *(uint32_t*)&AsL[ra][k16 + fc + 8];
                aL[ms][3] = *(uint32_t*)&AsL[ra + 8][k16 + fc + 8];
            }
#pragma unroll
            for (int ns = 0; ns < NS; ns++) {
                int cB = wn + ns * 8 + fr;
                int w0 = (k16 >> 1) + (lane & 3);
                int w1 = w0 + 4;
                if (BNN) {
                    int s2 = (cB >> 3) & 15;
                    w0 ^= s2; w1 ^= s2;
                }
                uint32_t bH[2], bL[2];
                bH[0] = *(uint32_t*)((char*)&BsH[0][0] + cB * 68 + 4 * w0);
                bH[1] = *(uint32_t*)((char*)&BsH[0][0] + cB * 68 + 4 * w1);
                bL[0] = *(uint32_t*)((char*)&BsL[0][0] + cB * 68 + 4 * w0);
                bL[1] = *(uint32_t*)((char*)&BsL[0][0] + cB * 68 + 4 * w1);
#pragma unroll
                for (int ms = 0; ms < MS; ms++) {
                    mma_bf16(acc[ms][ns], aH[ms], bH);
                    mma_bf16(acc[ms][ns], aH[ms], bL);
                    mma_bf16(acc[ms][ns], aL[ms], bH);
                }
            }
        }
    }

#pragma unroll
    for (int ms = 0; ms < MS; ms++) {
#pragma unroll
        for (int ns = 0; ns < NS; ns++) {
            int cr = wm + ms * 16 + fr;
            int cc = n0 + wn + ns * 8 + (lane & 3) * 2;
            float v0 = acc[ms][ns][0] * alpha, v1 = acc[ms][ns][1] * alpha;
            float v2 = acc[ms][ns][2] * alpha, v3 = acc[ms][ns][3] * alpha;
            if (ATOMIC) {
                atomicAdd(&Cb[(size_t)cr * ldc + cc], v0);
                atomicAdd(&Cb[(size_t)cr * ldc + cc + 1], v1);
                atomicAdd(&Cb[(size_t)(cr + 8) * ldc + cc], v2);
                atomicAdd(&Cb[(size_t)(cr + 8) * ldc + cc + 1], v3);
            } else {
                float2 p0 = {v0, v1}, p1 = {v2, v3};
                *(float2*)&Cb[(size_t)cr * ldc + cc] = p0;
                *(float2*)&Cb[(size_t)(cr + 8) * ldc + cc] = p1;
            }
        }
    }
}

// ---------------------------------------------------------------------------
__global__ void zero_k(float* __restrict__ p, int n) {
    int i = blockIdx.x * 256 + threadIdx.x;
    if (i < n) p[i] = 0.0f;
}

__global__ __launch_bounds__(256) void rmsnorm_k(
    const float* __restrict__ X, const float* __restrict__ W, float* __restrict__ Y)
{
    __shared__ float red[32];
    int b = blockIdx.x, t = threadIdx.x;
    const float* x = X + b * QLR;
    float s = 0.0f;
    for (int i = t; i < QLR; i += 256) { float v = x[i]; s += v * v; }
    for (int o = 16; o > 0; o >>= 1) s += __shfl_xor_sync(~0u, s, o);
    if ((t & 31) == 0) red[t >> 5] = s;
    __syncthreads();
    if (t < 32) {
        float v = (t < 8) ? red[t] : 0.0f;
        for (int o = 4; o > 0; o >>= 1) v += __shfl_xor_sync(~0u, v, o);
        if (t == 0) red[0] = v;
    }
    __syncthreads();
    float r = rsqrtf(red[0] / (float)QLR + 1e-6f);
    for (int i = t; i < QLR; i += 256) Y[b * QLR + i] = x[i] * r * W[i];
}

__global__ void rope_k(const float* __restrict__ Q, const int* __restrict__ pos,
                       float* __restrict__ QY, float scale)
{
    int bh = blockIdx.x;
    int b = bh >> 7, h = bh & 127;
    int i = threadIdx.x;
    int j = i & 31;
    float p = (float)pos[b];
    float invf = powf(10000.0f, -(float)j / 32.0f);
    float s, c;
    sincosf(p * invf, &s, &c);
    const float* q = Q + (size_t)b * NH * QHD + h * QHD + 128;
    float v;
    if (i < 32) v = q[2 * j] * c - q[2 * j + 1] * s;
    else        v = q[2 * j + 1] * c + q[2 * j] * s;
    QY[(size_t)b * NH * CKVD + h * CKVD + 512 + i] = v * scale;
}

// Row softmax over 4096; reads fp32 scores, writes bf16 hi/lo prob planes.
__global__ __launch_bounds__(256) void softmax_k(
    const float* __restrict__ S, __nv_bfloat16* __restrict__ PH,
    __nv_bfloat16* __restrict__ PL)
{
    __shared__ float red[32];
    size_t base = (size_t)blockIdx.x * KVLEN;
    int t = threadIdx.x;
    float4 v[4];
    float mx = -1e30f;
#pragma unroll
    for (int i = 0; i < 4; i++) {
        v[i] = *(const float4*)(S + base + t * 4 + i * 1024);
        mx = fmaxf(mx, fmaxf(fmaxf(v[i].x, v[i].y), fmaxf(v[i].z, v[i].w)));
    }
    for (int o = 16; o > 0; o >>= 1) mx = fmaxf(mx, __shfl_xor_sync(~0u, mx, o));
    if ((t & 31) == 0) red[t >> 5] = mx;
    __syncthreads();
    if (t < 32) {
        float m2 = (t < 8) ? red[t] : -1e30f;
        for (int o = 4; o > 0; o >>= 1) m2 = fmaxf(m2, __shfl_xor_sync(~0u, m2, o));
        if (t == 0) red[0] = m2;
    }
    __syncthreads();
    mx = red[0];
    __syncthreads();
    float sum = 0.0f;
#pragma unroll
    for (int i = 0; i < 4; i++) {
        v[i].x = __expf(v[i].x - mx); v[i].y = __expf(v[i].y - mx);
        v[i].z = __expf(v[i].z - mx); v[i].w = __expf(v[i].w - mx);
        sum += v[i].x + v[i].y + v[i].z + v[i].w;
    }
    for (int o = 16; o > 0; o >>= 1) sum += __shfl_xor_sync(~0u, sum, o);
    if ((t & 31) == 0) red[t >> 5] = sum;
    __syncthreads();
    if (t < 32) {
        float s2 = (t < 8) ? red[t] : 0.0f;
        for (int o = 4; o > 0; o >>= 1) s2 += __shfl_xor_sync(~0u, s2, o);
        if (t == 0) red[0] = s2;
    }
    __syncthreads();
    float inv = 1.0f / red[0];
#pragma unroll
    for (int i = 0; i < 4; i++) {
        float a = v[i].x * inv, bq = v[i].y * inv;
        float cc = v[i].z * inv, d = v[i].w * inv;
        uint32_t h0, l0, h1, l1;
        cvt2(a, bq, h0, l0);
        cvt2(cc, d, h1, l1);
        size_t idx = base + t * 4 + i * 1024;
        *(uint2*)(PH + idx) = make_uint2(h0, h1);
        *(uint2*)(PL + idx) = make_uint2(l0, l1);
    }
}

// ---------------------------------------------------------------------------
extern "C" void kernel_launch(void* const* d_in, const int* in_sizes, int n_in,
                              void* d_out, int out_size)
{
    const float* hq   = (const float*)d_in[0];
    const int*   pos  = (const int*)d_in[1];
    const float* ckv  = (const float*)d_in[2];
    const float* Wqa  = (const float*)d_in[3];
    const float* lnw  = (const float*)d_in[4];
    const float* Wqb  = (const float*)d_in[5];
    const float* Wkvb = (const float*)d_in[6];
    const float* Wo   = (const float*)d_in[7];
    float* out = (float*)d_out;

    float *qa, *qan, *q, *qry, *sc, *at, *o;
    __nv_bfloat16 *ckvH, *ckvL, *qryH, *qryL, *prH, *prL;
    cudaGetSymbolAddress((void**)&qa,   g_qa);
    cudaGetSymbolAddress((void**)&qan,  g_qan);
    cudaGetSymbolAddress((void**)&q,    g_q);
    cudaGetSymbolAddress((void**)&qry,  g_query);
    cudaGetSymbolAddress((void**)&sc,   g_scores);
    cudaGetSymbolAddress((void**)&at,   g_attn);
    cudaGetSymbolAddress((void**)&o,    g_o);
    cudaGetSymbolAddress((void**)&ckvH, g_ckvH);
    cudaGetSymbolAddress((void**)&ckvL, g_ckvL);
    cudaGetSymbolAddress((void**)&qryH, g_qryH);
    cudaGetSymbolAddress((void**)&qryL, g_qryL);
    cudaGetSymbolAddress((void**)&prH,  g_prH);
    cudaGetSymbolAddress((void**)&prL,  g_prL);

    cudaFuncSetAttribute(pipegemm<false>,
                         cudaFuncAttributeMaxDynamicSharedMemorySize, PIPE_SMEM);
    cudaFuncSetAttribute(pipegemm<true>,
                         cudaFuncAttributeMaxDynamicSharedMemorySize, PIPE_SMEM);

    const float scale = 1.0f / sqrtf(192.0f);

    // pre-split compressed_kv into bf16 hi/lo planes (302 MB read)
    cvt_plane<<<36864, 256>>>((const float4*)ckv, (uint2*)ckvH, (uint2*)ckvL,
                              NB * KVLEN * CKVD / 4);

    // zero split-K atomic destinations
    zero_k<<<192, 256>>>(qa, NB * QLR);
    zero_k<<<640, 256>>>(out, NB * HID);

    // q_a = hq @ Wq_a^T : M=32, N=1536, K=5120, split-K=8
    mmagemm<32, false, true><<<dim3(12, 8, 1), 256>>>(
        hq, HID, 0, Wqa, HID, 0, qa, QLR, 0, HID, 1.0f);

    rmsnorm_k<<<32, 256>>>(qa, lnw, qan);

    // q = qan @ Wq_b^T : M=32, N=24576, K=1536
    mmagemm<32, false, false><<<dim3(192, 1, 1), 256>>>(
        qan, QLR, 0, Wqb, QLR, 0, q, NH * QHD, 0, QLR, 1.0f);

    // RoPE -> query[..., 512:576] (scaled)
    rope_k<<<NB * NH, 64>>>(q, pos, qry, scale);

    // q_lat: per head M=32, N=512, K=128 (NN vs q_absorb) -> query[..., :512]
    mmagemm<32, true, false><<<dim3(4, 1, NH), 256>>>(
        q, NH * QHD, QHD,
        Wkvb, KVLR, 256 * KVLR,
        qry, NH * CKVD, CKVD,
        128, scale);

    // split query into bf16 hi/lo planes (9.4 MB)
    cvt_plane<<<2304, 256>>>((const float4*)qry, (uint2*)qryH, (uint2*)qryL,
                             NB * NH * CKVD / 4);

    // scores: per b, [128 heads] x [4096 kv], K=576 — pipelined NT
    pipegemm<false><<<dim3(32, NB), 256, PIPE_SMEM>>>(
        qryH, qryL, CKVD, NH * CKVD,
        ckvH, ckvL, CKVD, KVLEN * CKVD,
        sc, KVLEN, NH * KVLEN, CKVD);

    // softmax -> bf16 hi/lo probs
    softmax_k<<<NB * NH, 256>>>(sc, prH, prL);

    // attn: per b, [128 heads] x [512 lat], K=4096 — pipelined NN (ldmatrix.trans)
    pipegemm<true><<<dim3(4, NB), 256, PIPE_SMEM>>>(
        prH, prL, KVLEN, NH * KVLEN,
        ckvH, ckvL, CKVD, KVLEN * CKVD,
        at, KVLR, NH * KVLR, KVLEN);

    // o: per head M=32, N=128, K=512 (NT vs out_absorb)
    mmagemm<32, false, false><<<dim3(1, 1, NH), 256>>>(
        at, NH * KVLR, KVLR,
        Wkvb + 128 * KVLR, KVLR, 256 * KVLR,
        o, NH * 128, 128,
        KVLR, 1.0f);

    // out = o @ Wo^T : M=32, N=5120, K=16384, split-K=8
    mmagemm<32, false, true><<<dim3(40, 8, 1), 256>>>(
        o, NH * 128, 0, Wo, NH * 128, 0, out, HID, 0, NH * 128, 1.0f);
}

// round 14
// speedup vs baseline: 2.0937x; 1.0523x over previous
#include <cuda_runtime.h>
#include <cuda_bf16.h>
#include <math.h>
#include <stdint.h>

#define NB 32
#define NH 128
#define HID 5120
#define QLR 1536
#define KVLR 512
#define KVLEN 4096
#define CKVD 576
#define QHD 192

// ----------------------- device scratch (no allocs allowed) -----------------
__device__ __align__(16) float g_qa[NB * QLR];
__device__ __align__(16) float g_qan[NB * QLR];
__device__ __align__(16) float g_q[NB * NH * QHD];
__device__ __align__(16) float g_query[NB * NH * CKVD];
__device__ __align__(16) float g_scores[(size_t)NB * NH * KVLEN];   // 64 MB
__device__ __align__(16) float g_attn[NB * NH * KVLR];
__device__ __align__(16) float g_o[NB * NH * 128];

__device__ __align__(16) __nv_bfloat16 g_ckvH[(size_t)NB * KVLEN * CKVD];  // 151 MB
__device__ __align__(16) __nv_bfloat16 g_ckvL[(size_t)NB * KVLEN * CKVD];  // 151 MB
__device__ __align__(16) __nv_bfloat16 g_qryH[NB * NH * CKVD];
__device__ __align__(16) __nv_bfloat16 g_qryL[NB * NH * CKVD];
__device__ __align__(16) __nv_bfloat16 g_prH[(size_t)NB * NH * KVLEN];     // 33.5 MB
__device__ __align__(16) __nv_bfloat16 g_prL[(size_t)NB * NH * KVLEN];     // 33.5 MB

// ----------------------- helpers -------------------------------------------
__device__ __forceinline__ uint32_t pkbf2(float a, float b) {
    __nv_bfloat162 t = __floats2bfloat162_rn(a, b);
    return *(uint32_t*)&t;
}
__device__ __forceinline__ float bfhi(float x) {
    return __bfloat162float(__float2bfloat16_rn(x));
}
__device__ __forceinline__ void mma_bf16(float* c, const uint32_t* a, const uint32_t* b) {
    asm volatile(
        "mma.sync.aligned.m16n8k16.row.col.f32.bf16.bf16.f32 "
        "{%0,%1,%2,%3},{%4,%5,%6,%7},{%8,%9},{%0,%1,%2,%3};\n"
        : "+f"(c[0]), "+f"(c[1]), "+f"(c[2]), "+f"(c[3])
        : "r"(a[0]), "r"(a[1]), "r"(a[2]), "r"(a[3]), "r"(b[0]), "r"(b[1]));
}
__device__ __forceinline__ void cvt2(float a, float b, uint32_t& H, uint32_t& L) {
    asm("cvt.rn.satfinite.bf16x2.f32 %0, %1, %2;" : "=r"(H) : "f"(b), "f"(a));
    float ha = __uint_as_float(H << 16);
    float hb = __uint_as_float(H & 0xffff0000u);
    asm("cvt.rn.satfinite.bf16x2.f32 %0, %1, %2;" : "=r"(L) : "f"(b - hb), "f"(a - ha));
}
__device__ __forceinline__ uint32_t smem_u32(const void* p) {
    uint32_t a;
    asm("{ .reg .u64 t; cvta.to.shared.u64 t, %1; cvt.u32.u64 %0, t; }"
        : "=r"(a) : "l"(p));
    return a;
}
__device__ __forceinline__ void cpasync(uint32_t s, const void* g) {
    asm volatile("cp.async.cg.shared.global [%0],[%1],16;" :: "r"(s), "l"(g) : "memory");
}
#define CP_COMMIT() asm volatile("cp.async.commit_group;" ::: "memory")
#define LDSM4(r, ad) \
    asm volatile("ldmatrix.sync.aligned.m8n8.x4.shared.b16 {%0,%1,%2,%3},[%4];" \
        : "=r"((r)[0]), "=r"((r)[1]), "=r"((r)[2]), "=r"((r)[3]) : "r"(ad))
#define LDSM4T(r, ad) \
    asm volatile("ldmatrix.sync.aligned.m8n8.x4.trans.shared.b16 {%0,%1,%2,%3},[%4];" \
        : "=r"((r)[0]), "=r"((r)[1]), "=r"((r)[2]), "=r"((r)[3]) : "r"(ad))

#define PIPE_SMEM 196608   /* 3 stages x 64KB */

// ---------------------------------------------------------------------------
// Pipelined bf16 hi/lo GEMM on pre-split planes. C fp32 = sum of 3 passes.
//   BT=false: B planes are [n][k] rows (NT).  BT=true: B planes are [k][n] (NN).
// CTA tile 128x128, KC=64, 256 threads, 3-stage cp.async pipeline.
// grid.x = N/128 tiles, grid.y = batch, grid.z = split-K (AT -> atomics).
// ---------------------------------------------------------------------------
template <bool BT, bool AT>
__global__ __launch_bounds__(256, 1) void pipegemm(
    const __nv_bfloat16* __restrict__ AH, const __nv_bfloat16* __restrict__ AL,
    int lda, int sA,
    const __nv_bfloat16* __restrict__ BH, const __nv_bfloat16* __restrict__ BL,
    int ldb, int sB,
    float* __restrict__ C, int ldc, int sC, int K)
{
    extern __shared__ __align__(1024) char sm[];
    const uint32_t sb = smem_u32(sm);
    const int tid = threadIdx.x, lane = tid & 31, warp = tid >> 5;
    const int b = blockIdx.y;
    const __nv_bfloat16* AHb = AH + (size_t)b * sA;
    const __nv_bfloat16* ALb = AL + (size_t)b * sA;
    const __nv_bfloat16* BHb = BH + (size_t)b * sB;
    const __nv_bfloat16* BLb = BL + (size_t)b * sB;
    float* Cb = C + (size_t)b * sC;
    const int n0 = blockIdx.x * 128;
    const int kseg = K / (int)gridDim.z;
    const int kst = blockIdx.z * kseg;
    const int nslab = kseg >> 6;

    const int wm = (warp >> 1) * 32;
    const int wn = (warp & 1) * 64;

    float acc[2][8][4];
#pragma unroll
    for (int i = 0; i < 2; i++)
#pragma unroll
        for (int j = 0; j < 8; j++)
#pragma unroll
            for (int q = 0; q < 4; q++) acc[i][j][q] = 0.0f;

    auto issue = [&](int s) {
        const int kp = kst + s * 64;
        const uint32_t st = sb + (s % 3) * 65536;
#pragma unroll
        for (int i = 0; i < 4; i++) {
            int lin = tid + i * 256;
            int r = lin >> 3, c = lin & 7;
            uint32_t so = st + r * 128 + ((c ^ (r & 7)) << 4);
            const char* gh = (const char*)(AHb + (size_t)r * lda + kp) + (c << 4);
            const char* gl = (const char*)(ALb + (size_t)r * lda + kp) + (c << 4);
            cpasync(so, gh);
            cpasync(so + 16384, gl);
        }
        if (BT) {
#pragma unroll
            for (int i = 0; i < 4; i++) {
                int lin = tid + i * 256;
                int r = lin >> 4, c = lin & 15;
                uint32_t so = st + 32768 + r * 256 + ((c ^ (r & 7)) << 4);
                const char* gh = (const char*)(BHb + (size_t)(kp + r) * ldb + n0) + (c << 4);
                const char* gl = (const char*)(BLb + (size_t)(kp + r) * ldb + n0) + (c << 4);
                cpasync(so, gh);
                cpasync(so + 16384, gl);
            }
        } else {
#pragma unroll
            for (int i = 0; i < 4; i++) {
                int lin = tid + i * 256;
                int r = lin >> 3, c = lin & 7;
                uint32_t so = st + 32768 + r * 128 + ((c ^ (r & 7)) << 4);
                const char* gh = (const char*)(BHb + (size_t)(n0 + r) * ldb + kp) + (c << 4);
                const char* gl = (const char*)(BLb + (size_t)(n0 + r) * ldb + kp) + (c << 4);
                cpasync(so, gh);
                cpasync(so + 16384, gl);
            }
        }
        CP_COMMIT();
    };

    issue(0);
    if (nslab > 1) issue(1);

    for (int s = 0; s < nslab; s++) {
        if (s + 2 < nslab) {
            issue(s + 2);
            asm volatile("cp.async.wait_group 2;" ::: "memory");
        } else if (s + 1 < nslab) {
            asm volatile("cp.async.wait_group 1;" ::: "memory");
        } else {
            asm volatile("cp.async.wait_group 0;" ::: "memory");
        }
        __syncthreads();
        const uint32_t st = sb + (s % 3) * 65536;

#pragma unroll
        for (int kk = 0; kk < 4; kk++) {
            uint32_t aH[2][4], aL[2][4];
#pragma unroll
            for (int ms = 0; ms < 2; ms++) {
                int r = wm + ms * 16 + ((lane >> 3) & 1) * 8 + (lane & 7);
                int c = 2 * kk + (lane >> 4);
                uint32_t ad = st + r * 128 + ((c ^ (r & 7)) << 4);
                LDSM4(aH[ms], ad);
                LDSM4(aL[ms], ad + 16384);
            }
            uint32_t bH[8][2], bL[8][2];
            if (BT) {
#pragma unroll
                for (int j = 0; j < 4; j++) {
                    int r = kk * 16 + ((lane >> 3) & 1) * 8 + (lane & 7);
                    int c = (wn >> 3) + 2 * j + (lane >> 4);
                    uint32_t ad = st + 32768 + r * 256 + ((c ^ (r & 7)) << 4);
                    uint32_t t[4], u[4];
                    LDSM4T(t, ad);
                    LDSM4T(u, ad + 16384);
                    bH[2 * j][0] = t[0]; bH[2 * j][1] = t[1];
                    bH[2 * j + 1][0] = t[2]; bH[2 * j + 1][1] = t[3];
                    bL[2 * j][0] = u[0]; bL[2 * j][1] = u[1];
                    bL[2 * j + 1][0] = u[2]; bL[2 * j + 1][1] = u[3];
                }
            } else {
#pragma unroll
                for (int j = 0; j < 4; j++) {
                    int r = wn + j * 16 + ((lane >> 4) & 1) * 8 + (lane & 7);
                    int c = 2 * kk + ((lane >> 3) & 1);
                    uint32_t ad = st + 32768 + r * 128 + ((c ^ (r & 7)) << 4);
                    uint32_t t[4], u[4];
                    LDSM4(t, ad);
                    LDSM4(u, ad + 16384);
                    bH[2 * j][0] = t[0]; bH[2 * j][1] = t[1];
                    bH[2 * j + 1][0] = t[2]; bH[2 * j + 1][1] = t[3];
                    bL[2 * j][0] = u[0]; bL[2 * j][1] = u[1];
                    bL[2 * j + 1][0] = u[2]; bL[2 * j + 1][1] = u[3];
                }
            }
#pragma unroll
            for (int ns = 0; ns < 8; ns++) {
#pragma unroll
                for (int ms = 0; ms < 2; ms++) {
                    mma_bf16(acc[ms][ns], aH[ms], bH[ns]);
                    mma_bf16(acc[ms][ns], aH[ms], bL[ns]);
                    mma_bf16(acc[ms][ns], aL[ms], bH[ns]);
                }
            }
        }
        __syncthreads();
    }

#pragma unroll
    for (int ms = 0; ms < 2; ms++) {
#pragma unroll
        for (int ns = 0; ns < 8; ns++) {
            int r = wm + ms * 16 + (lane >> 2);
            int c = n0 + wn + ns * 8 + (lane & 3) * 2;
            if (AT) {
                atomicAdd(&Cb[(size_t)r * ldc + c], acc[ms][ns][0]);
                atomicAdd(&Cb[(size_t)r * ldc + c + 1], acc[ms][ns][1]);
                atomicAdd(&Cb[(size_t)(r + 8) * ldc + c], acc[ms][ns][2]);
                atomicAdd(&Cb[(size_t)(r + 8) * ldc + c + 1], acc[ms][ns][3]);
            } else {
                float2 p0 = {acc[ms][ns][0], acc[ms][ns][1]};
                float2 p1 = {acc[ms][ns][2], acc[ms][ns][3]};
                *(float2*)&Cb[(size_t)r * ldc + c] = p0;
                *(float2*)&Cb[(size_t)(r + 8) * ldc + c] = p1;
            }
        }
    }
}

// ---------------------------------------------------------------------------
__global__ void cvt_plane(const float4* __restrict__ X, uint2* __restrict__ H,
                          uint2* __restrict__ L, int n4)
{
    int i = blockIdx.x * 256 + threadIdx.x;
    int stride = gridDim.x * 256;
    for (; i < n4; i += stride) {
        float4 v = X[i];
        uint32_t h0, l0, h1, l1;
        cvt2(v.x, v.y, h0, l0);
        cvt2(v.z, v.w, h1, l1);
        H[i] = make_uint2(h0, h1);
        L[i] = make_uint2(l0, l1);
    }
}

// ---------------------------------------------------------------------------
// mma.sync GEMM for small M=32 weight GEMMs (memory-streaming)
// ---------------------------------------------------------------------------
template <int TM, bool BNN, bool ATOMIC>
__global__ __launch_bounds__(256, 2) void mmagemm(
    const float* __restrict__ A, int lda, int sA,
    const float* __restrict__ B, int ldb, int sB,
    float* __restrict__ C, int ldc, int sC,
    int K, float alpha)
{
    constexpr int KC = 32;
    constexpr int WM = (TM == 128) ? 4 : 2;
    constexpr int MS = TM / (WM * 16);
    constexpr int NS = 128 / ((8 / WM) * 8);
    constexpr int APF = (TM * KC) / 1024;

    __shared__ __align__(16) __nv_bfloat16 AsH[TM][34];
    __shared__ __align__(16) __nv_bfloat16 AsL[TM][34];
    __shared__ __align__(16) __nv_bfloat16 BsH[128][34];
    __shared__ __align__(16) __nv_bfloat16 BsL[128][34];

    const float* Ab = A + (size_t)blockIdx.z * sA;
    const float* Bb = B + (size_t)blockIdx.z * sB;
    float* Cb = C + (size_t)blockIdx.z * sC;

    const int n0 = blockIdx.x * 128;
    const int kseg = K / (int)gridDim.y;
    const int kst = blockIdx.y * kseg;

    const int tid = threadIdx.x;
    const int lane = tid & 31;
    const int warp = tid >> 5;
    const int wm = (TM == 128) ? ((warp >> 1) * 32) : ((warp & 1) * 16);
    const int wn = (TM == 128) ? ((warp & 1) * 64) : ((warp >> 1) * 32);
    const int fr = lane >> 2;
    const int fc = (lane & 3) * 2;

    float acc[MS][NS][4];
#pragma unroll
    for (int i = 0; i < MS; i++)
#pragma unroll
        for (int j = 0; j < NS; j++)
#pragma unroll
            for (int q = 0; q < 4; q++) acc[i][j][q] = 0.0f;

    float4 pa[APF];
    float4 pbt[4];
    float4 pb0[2], pb1[2];

    auto loadA = [&](int kp) {
#pragma unroll
        for (int i = 0; i < APF; i++) {
            int lin = tid + i * 256;
            int r = lin >> 3, k4 = (lin & 7) * 4;
            pa[i] = *(const float4*)(Ab + (size_t)r * lda + kp + k4);
        }
    };
    auto storeA = [&]() {
#pragma unroll
        for (int i = 0; i < APF; i++) {
            int lin = tid + i * 256;
            int r = lin >> 3, k4 = (lin & 7) * 4;
            float4 v = pa[i];
            float hx = bfhi(v.x), hy = bfhi(v.y), hz = bfhi(v.z), hw = bfhi(v.w);
            uint32_t* dh = (uint32_t*)&AsH[r][k4];
            uint32_t* dl = (uint32_t*)&AsL[r][k4];
            dh[0] = pkbf2(hx, hy); dh[1] = pkbf2(hz, hw);
            dl[0] = pkbf2(v.x - hx, v.y - hy); dl[1] = pkbf2(v.z - hz, v.w - hw);
        }
    };
    auto loadB = [&](int kp) {
        if (BNN) {
#pragma unroll
            for (int g = 0; g < 2; g++) {
                int slot = tid + g * 256;
                int kpp = slot >> 5;
                int n = (slot & 31) * 4;
                const float* r0 = Bb + (size_t)(kp + 2 * kpp) * ldb + n0 + n;
                pb0[g] = *(const float4*)r0;
                pb1[g] = *(const float4*)(r0 + ldb);
            }
        } else {
#pragma unroll
            for (int i = 0; i < 4; i++) {
                int lin = tid + i * 256;
                int nr = lin >> 3, k4 = (lin & 7) * 4;
                pbt[i] = *(const float4*)(Bb + (size_t)(n0 + nr) * ldb + kp + k4);
            }
        }
    };
    auto storeB = [&]() {
        if (BNN) {
#pragma unroll
            for (int g = 0; g < 2; g++) {
                int slot = tid + g * 256;
                int kpp = slot >> 5;
                int n = (slot & 31) * 4;
                float r0[4] = {pb0[g].x, pb0[g].y, pb0[g].z, pb0[g].w};
                float r1[4] = {pb1[g].x, pb1[g].y, pb1[g].z, pb1[g].w};
#pragma unroll
                for (int j = 0; j < 4; j++) {
                    int nn = n + j;
                    int w = kpp ^ ((nn >> 3) & 15);
                    float h0 = bfhi(r0[j]), h1 = bfhi(r1[j]);
                    *(uint32_t*)((char*)&BsH[0][0] + nn * 68 + 4 * w) = pkbf2(h0, h1);
                    *(uint32_t*)((char*)&BsL[0][0] + nn * 68 + 4 * w) =
                        pkbf2(r0[j] - h0, r1[j] - h1);
                }
            }
        } else {
#pragma unroll
            for (int i = 0; i < 4; i++) {
                int lin = tid + i * 256;
                int nr = lin >> 3, k4 = (lin & 7) * 4;
                float4 v = pbt[i];
                float hx = bfhi(v.x), hy = bfhi(v.y), hz = bfhi(v.z), hw = bfhi(v.w);
                uint32_t* dh = (uint32_t*)&BsH[nr][k4];
                uint32_t* dl = (uint32_t*)&BsL[nr][k4];
                dh[0] = pkbf2(hx, hy); dh[1] = pkbf2(hz, hw);
                dl[0] = pkbf2(v.x - hx, v.y - hy); dl[1] = pkbf2(v.z - hz, v.w - hw);
            }
        }
    };

    loadA(kst);
    loadB(kst);

    const int kend = kst + kseg;
    for (int kp = kst; kp < kend; kp += KC) {
        __syncthreads();
        storeA();
        storeB();
        __syncthreads();
        if (kp + KC < kend) { loadA(kp + KC); loadB(kp + KC); }

#pragma unroll
        for (int k16 = 0; k16 < KC; k16 += 16) {
            uint32_t aH[MS][4], aL[MS][4];
#pragma unroll
            for (int ms = 0; ms < MS; ms++) {
                int ra = wm + ms * 16 + fr;
                aH[ms][0] = *(uint32_t*)&AsH[ra][k16 + fc];
                aH[ms][1] = *(uint32_t*)&AsH[ra + 8][k16 + fc];
                aH[ms][2] = *(uint32_t*)&AsH[ra][k16 + fc + 8];
                aH[ms][3] = *(uint32_t*)&AsH[ra + 8][k16 + fc + 8];
                aL[ms][0] = *(uint32_t*)&AsL[ra][k16 + fc];
                aL[ms][1] = *(uint32_t*)&AsL[ra + 8][k16 + fc];
                aL[ms][2] = *(uint32_t*)&AsL[ra][k16 + fc + 8];
                aL[ms][3] = *(uint32_t*)&AsL[ra + 8][k16 + fc + 8];
            }
#pragma unroll
            for (int ns = 0; ns < NS; ns++) {
                int cB = wn + ns * 8 + fr;
                int w0 = (k16 >> 1) + (lane & 3);
                int w1 = w0 + 4;
                if (BNN) {
                    int s2 = (cB >> 3) & 15;
                    w0 ^= s2; w1 ^= s2;
                }
                uint32_t bH[2], bL[2];
                bH[0] = *(uint32_t*)((char*)&BsH[0][0] + cB * 68 + 4 * w0);
                bH[1] = *(uint32_t*)((char*)&BsH[0][0] + cB * 68 + 4 * w1);
                bL[0] = *(uint32_t*)((char*)&BsL[0][0] + cB * 68 + 4 * w0);
                bL[1] = *(uint32_t*)((char*)&BsL[0][0] + cB * 68 + 4 * w1);
#pragma unroll
                for (int ms = 0; ms < MS; ms++) {
                    mma_bf16(acc[ms][ns], aH[ms], bH);
                    mma_bf16(acc[ms][ns], aH[ms], bL);
                    mma_bf16(acc[ms][ns], aL[ms], bH);
                }
            }
        }
    }

#pragma unroll
    for (int ms = 0; ms < MS; ms++) {
#pragma unroll
        for (int ns = 0; ns < NS; ns++) {
            int cr = wm + ms * 16 + fr;
            int cc = n0 + wn + ns * 8 + (lane & 3) * 2;
            float v0 = acc[ms][ns][0] * alpha, v1 = acc[ms][ns][1] * alpha;
            float v2 = acc[ms][ns][2] * alpha, v3 = acc[ms][ns][3] * alpha;
            if (ATOMIC) {
                atomicAdd(&Cb[(size_t)cr * ldc + cc], v0);
                atomicAdd(&Cb[(size_t)cr * ldc + cc + 1], v1);
                atomicAdd(&Cb[(size_t)(cr + 8) * ldc + cc], v2);
                atomicAdd(&Cb[(size_t)(cr + 8) * ldc + cc + 1], v3);
            } else {
                float2 p0 = {v0, v1}, p1 = {v2, v3};
                *(float2*)&Cb[(size_t)cr * ldc + cc] = p0;
                *(float2*)&Cb[(size_t)(cr + 8) * ldc + cc] = p1;
            }
        }
    }
}

// ---------------------------------------------------------------------------
__global__ void zero_k(float* __restrict__ p, int n) {
    int i = blockIdx.x * 256 + threadIdx.x;
    if (i < n) p[i] = 0.0f;
}

__global__ __launch_bounds__(256) void rmsnorm_k(
    const float* __restrict__ X, const float* __restrict__ W, float* __restrict__ Y)
{
    __shared__ float red[32];
    int b = blockIdx.x, t = threadIdx.x;
    const float* x = X + b * QLR;
    float s = 0.0f;
    for (int i = t; i < QLR; i += 256) { float v = x[i]; s += v * v; }
    for (int o = 16; o > 0; o >>= 1) s += __shfl_xor_sync(~0u, s, o);
    if ((t & 31) == 0) red[t >> 5] = s;
    __syncthreads();
    if (t < 32) {
        float v = (t < 8) ? red[t] : 0.0f;
        for (int o = 4; o > 0; o >>= 1) v += __shfl_xor_sync(~0u, v, o);
        if (t == 0) red[0] = v;
    }
    __syncthreads();
    float r = rsqrtf(red[0] / (float)QLR + 1e-6f);
    for (int i = t; i < QLR; i += 256) Y[b * QLR + i] = x[i] * r * W[i];
}

__global__ void rope_k(const float* __restrict__ Q, const int* __restrict__ pos,
                       float* __restrict__ QY, float scale)
{
    int bh = blockIdx.x;
    int b = bh >> 7, h = bh & 127;
    int i = threadIdx.x;
    int j = i & 31;
    float p = (float)pos[b];
    float invf = powf(10000.0f, -(float)j / 32.0f);
    float s, c;
    sincosf(p * invf, &s, &c);
    const float* q = Q + (size_t)b * NH * QHD + h * QHD + 128;
    float v;
    if (i < 32) v = q[2 * j] * c - q[2 * j + 1] * s;
    else        v = q[2 * j + 1] * c + q[2 * j] * s;
    QY[(size_t)b * NH * CKVD + h * CKVD + 512 + i] = v * scale;
}

// Row softmax over 4096; reads fp32 scores, writes bf16 hi/lo prob planes.
__global__ __launch_bounds__(256) void softmax_k(
    const float* __restrict__ S, __nv_bfloat16* __restrict__ PH,
    __nv_bfloat16* __restrict__ PL)
{
    __shared__ float red[32];
    size_t base = (size_t)blockIdx.x * KVLEN;
    int t = threadIdx.x;
    float4 v[4];
    float mx = -1e30f;
#pragma unroll
    for (int i = 0; i < 4; i++) {
        v[i] = *(const float4*)(S + base + t * 4 + i * 1024);
        mx = fmaxf(mx, fmaxf(fmaxf(v[i].x, v[i].y), fmaxf(v[i].z, v[i].w)));
    }
    for (int o = 16; o > 0; o >>= 1) mx = fmaxf(mx, __shfl_xor_sync(~0u, mx, o));
    if ((t & 31) == 0) red[t >> 5] = mx;
    __syncthreads();
    if (t < 32) {
        float m2 = (t < 8) ? red[t] : -1e30f;
        for (int o = 4; o > 0; o >>= 1) m2 = fmaxf(m2, __shfl_xor_sync(~0u, m2, o));
        if (t == 0) red[0] = m2;
    }
    __syncthreads();
    mx = red[0];
    __syncthreads();
    float sum = 0.0f;
#pragma unroll
    for (int i = 0; i < 4; i++) {
        v[i].x = __expf(v[i].x - mx); v[i].y = __expf(v[i].y - mx);
        v[i].z = __expf(v[i].z - mx); v[i].w = __expf(v[i].w - mx);
        sum += v[i].x + v[i].y + v[i].z + v[i].w;
    }
    for (int o = 16; o > 0; o >>= 1) sum += __shfl_xor_sync(~0u, sum, o);
    if ((t & 31) == 0) red[t >> 5] = sum;
    __syncthreads();
    if (t < 32) {
        float s2 = (t < 8) ? red[t] : 0.0f;
        for (int o = 4; o > 0; o >>= 1) s2 += __shfl_xor_sync(~0u, s2, o);
        if (t == 0) red[0] = s2;
    }
    __syncthreads();
    float inv = 1.0f / red[0];
#pragma unroll
    for (int i = 0; i < 4; i++) {
        float a = v[i].x * inv, bq = v[i].y * inv;
        float cc = v[i].z * inv, d = v[i].w * inv;
        uint32_t h0, l0, h1, l1;
        cvt2(a, bq, h0, l0);
        cvt2(cc, d, h1, l1);
        size_t idx = base + t * 4 + i * 1024;
        *(uint2*)(PH + idx) = make_uint2(h0, h1);
        *(uint2*)(PL + idx) = make_uint2(l0, l1);
    }
}

// ---------------------------------------------------------------------------
extern "C" void kernel_launch(void* const* d_in, const int* in_sizes, int n_in,
                              void* d_out, int out_size)
{
    const float* hq   = (const float*)d_in[0];
    const int*   pos  = (const int*)d_in[1];
    const float* ckv  = (const float*)d_in[2];
    const float* Wqa  = (const float*)d_in[3];
    const float* lnw  = (const float*)d_in[4];
    const float* Wqb  = (const float*)d_in[5];
    const float* Wkvb = (const float*)d_in[6];
    const float* Wo   = (const float*)d_in[7];
    float* out = (float*)d_out;

    float *qa, *qan, *q, *qry, *sc, *at, *o;
    __nv_bfloat16 *ckvH, *ckvL, *qryH, *qryL, *prH, *prL;
    cudaGetSymbolAddress((void**)&qa,   g_qa);
    cudaGetSymbolAddress((void**)&qan,  g_qan);
    cudaGetSymbolAddress((void**)&q,    g_q);
    cudaGetSymbolAddress((void**)&qry,  g_query);
    cudaGetSymbolAddress((void**)&sc,   g_scores);
    cudaGetSymbolAddress((void**)&at,   g_attn);
    cudaGetSymbolAddress((void**)&o,    g_o);
    cudaGetSymbolAddress((void**)&ckvH, g_ckvH);
    cudaGetSymbolAddress((void**)&ckvL, g_ckvL);
    cudaGetSymbolAddress((void**)&qryH, g_qryH);
    cudaGetSymbolAddress((void**)&qryL, g_qryL);
    cudaGetSymbolAddress((void**)&prH,  g_prH);
    cudaGetSymbolAddress((void**)&prL,  g_prL);

    cudaFuncSetAttribute(pipegemm<false, false>,
                         cudaFuncAttributeMaxDynamicSharedMemorySize, PIPE_SMEM);
    cudaFuncSetAttribute(pipegemm<true, true>,
                         cudaFuncAttributeMaxDynamicSharedMemorySize, PIPE_SMEM);

    const float scale = 1.0f / sqrtf(192.0f);

    // pre-split compressed_kv into bf16 hi/lo planes (302 MB read)
    cvt_plane<<<36864, 256>>>((const float4*)ckv, (uint2*)ckvH, (uint2*)ckvL,
                              NB * KVLEN * CKVD / 4);

    // zero all split-K atomic destinations
    zero_k<<<192, 256>>>(qa, NB * QLR);
    zero_k<<<640, 256>>>(out, NB * HID);
    zero_k<<<3072, 256>>>(q, NB * NH * QHD);
    zero_k<<<2048, 256>>>(o, NB * NH * 128);
    zero_k<<<8192, 256>>>(at, NB * NH * KVLR);

    // q_a = hq @ Wq_a^T : M=32, N=1536, K=5120, split-K=20 (240 CTAs)
    mmagemm<32, false, true><<<dim3(12, 20, 1), 256>>>(
        hq, HID, 0, Wqa, HID, 0, qa, QLR, 0, HID, 1.0f);

    rmsnorm_k<<<32, 256>>>(qa, lnw, qan);

    // q = qan @ Wq_b^T : M=32, N=24576, K=1536, split-K=2 (384 CTAs)
    mmagemm<32, false, true><<<dim3(192, 2, 1), 256>>>(
        qan, QLR, 0, Wqb, QLR, 0, q, NH * QHD, 0, QLR, 1.0f);

    // RoPE -> query[..., 512:576] (scaled)
    rope_k<<<NB * NH, 64>>>(q, pos, qry, scale);

    // q_lat: per head M=32, N=512, K=128 (NN vs q_absorb) -> query[..., :512]
    mmagemm<32, true, false><<<dim3(4, 1, NH), 256>>>(
        q, NH * QHD, QHD,
        Wkvb, KVLR, 256 * KVLR,
        qry, NH * CKVD, CKVD,
        128, scale);

    // split query into bf16 hi/lo planes (9.4 MB)
    cvt_plane<<<2304, 256>>>((const float4*)qry, (uint2*)qryH, (uint2*)qryL,
                             NB * NH * CKVD / 4);

    // scores: per b, [128 heads] x [4096 kv], K=576 — pipelined NT (1024 CTAs)
    pipegemm<false, false><<<dim3(32, NB, 1), 256, PIPE_SMEM>>>(
        qryH, qryL, CKVD, NH * CKVD,
        ckvH, ckvL, CKVD, KVLEN * CKVD,
        sc, KVLEN, NH * KVLEN, CKVD);

    // softmax -> bf16 hi/lo probs
    softmax_k<<<NB * NH, 256>>>(sc, prH, prL);

    // attn: per b, [128 heads] x [512 lat], K=4096 — pipelined NN, split-K=4 (512 CTAs)
    pipegemm<true, true><<<dim3(4, NB, 4), 256, PIPE_SMEM>>>(
        prH, prL, KVLEN, NH * KVLEN,
        ckvH, ckvL, CKVD, KVLEN * CKVD,
        at, KVLR, NH * KVLR, KVLEN);

    // o: per head M=32, N=128, K=512 (NT vs out_absorb), split-K=4 (512 CTAs)
    mmagemm<32, false, true><<<dim3(1, 4, NH), 256>>>(
        at, NH * KVLR, KVLR,
        Wkvb + 128 * KVLR, KVLR, 256 * KVLR,
        o, NH * 128, 128,
        KVLR, 1.0f);

    // out = o @ Wo^T : M=32, N=5120, K=16384, split-K=16 (640 CTAs)
    mmagemm<32, false, true><<<dim3(40, 16, 1), 256>>>(
        o, NH * 128, 0, Wo, NH * 128, 0, out, HID, 0, NH * 128, 1.0f);
}